// round 1
// baseline (speedup 1.0000x reference)
#include <cuda_runtime.h>
#include <math.h>

#define DT 0.001f
#define STEPS 128
#define UNITS 512
#define BATCH 64
#define MROWS (STEPS * BATCH)   // 8192
#define ACTION_DIM 256

// ---------------- scratch (device globals; no allocations allowed) ----------------
__device__ float g_states[MROWS * 1024];     // hopf states z1..z128, row m = t*64 + b, [x(512), y(512)]
__device__ float g_act1[MROWS * 2048];       // layer0 output [x1(1024), y1(1024)]
__device__ float g_act2[MROWS * 1024];       // layer1 output [x2(512),  y2(512)]
__device__ float g_P0[1024 * 2048];          // packed layer0 weights (2K x 2N), K=512,N=1024
__device__ float g_P1[2048 * 1024];          // packed layer1 weights, K=1024,N=512
__device__ float g_P2[1024 * 256];           // packed layer2 weights (real half only), K=512,N=256

// ---------------- weight packing ----------------
// Full complex pack: P (2K x 2N): [[Wr, Wi], [-Wi, Wr]]
__global__ void pack_full(const float* __restrict__ Wr, const float* __restrict__ Wi,
                          float* __restrict__ P, int K, int N) {
    int idx = blockIdx.x * blockDim.x + threadIdx.x;
    int total = 4 * K * N;
    if (idx >= total) return;
    int N2 = 2 * N;
    int row = idx / N2;
    int col = idx - row * N2;
    float v;
    if (row < K) v = (col < N) ? Wr[row * N + col] : Wi[row * N + (col - N)];
    else         v = (col < N) ? -Wi[(row - K) * N + col] : Wr[(row - K) * N + (col - N)];
    P[idx] = v;
}

// Real-output-only pack: P (2K x N): [Wr; -Wi]
__global__ void pack_half(const float* __restrict__ Wr, const float* __restrict__ Wi,
                          float* __restrict__ P, int K, int N) {
    int idx = blockIdx.x * blockDim.x + threadIdx.x;
    int total = 2 * K * N;
    if (idx >= total) return;
    int row = idx / N;
    int col = idx - row * N;
    P[idx] = (row < K) ? Wr[row * N + col] : -Wi[(row - K) * N + col];
}

// ---------------- hopf chain ----------------
// 64*512 = 32768 threads; each owns one (batch, unit) pair; fully independent.
__global__ void hopf_kernel(const float* __restrict__ z0, const float* __restrict__ omega,
                            const float* __restrict__ bpar, float* __restrict__ states,
                            float* __restrict__ out_z1) {
    int tid = blockIdx.x * blockDim.x + threadIdx.x;
    if (tid >= BATCH * UNITS) return;
    int bi = tid / UNITS;
    int i  = tid - bi * UNITS;
    float x = z0[bi * 1024 + i];
    float y = z0[bi * 1024 + UNITS + i];
    float w = omega[bi] * (float)(i + 1);
    float bb = bpar[bi * UNITS + i];
#pragma unroll 4
    for (int t = 0; t < STEPS; t++) {
        float r2 = x * x + y * y;
        float g = bb - r2;
        float dx = g * x - w * y;
        float dy = g * y + w * x;
        x += DT * dx;
        y += DT * dy;
        float* row = states + ((size_t)(t * BATCH + bi)) * 1024;
        row[i] = x;
        row[UNITS + i] = y;
        if (t == 0) {
            out_z1[bi * 1024 + i] = x;
            out_z1[bi * 1024 + UNITS + i] = y;
        }
    }
}

// ---------------- tiled SGEMM + bias + tanh ----------------
// C[M x N] = tanh(A[M x K] @ P[K x N] + bias), bias(n) = n < Nh ? blo[n] : bhi[n-Nh]
// BM=BN=128, BK=8, 256 threads, 8x8 micro-tile (split 4+4 in each dim).
#define BM 128
#define BN 128
#define BK 8
#define PADA 136   // 136 % 32 == 8 -> conflict-free column-major A-tile stores

template<bool SCATTER>
__global__ __launch_bounds__(256)
void gemm_bias_tanh(const float* __restrict__ A, const float* __restrict__ P,
                    const float* __restrict__ blo, const float* __restrict__ bhi, int Nh,
                    float* __restrict__ C, int M, int N, int K) {
    __shared__ float As[BK][PADA];
    __shared__ float Bs[BK][BN];

    int bm = blockIdx.y * BM;
    int bn = blockIdx.x * BN;
    int tid = threadIdx.x;

    // A tile loaders: pairs of threads share a row; 32B contiguous per row
    int a_row = tid >> 1;
    int a_col = (tid & 1) * 4;
    // B tile loaders: fully coalesced 512B rows
    int b_row = tid >> 5;
    int b_col = (tid & 31) * 4;

    int tx = tid & 15;   // column group
    int ty = tid >> 4;   // row group

    float acc[8][8];
#pragma unroll
    for (int i = 0; i < 8; i++)
#pragma unroll
        for (int j = 0; j < 8; j++) acc[i][j] = 0.0f;

    const float* Aptr = A + (size_t)(bm + a_row) * K + a_col;
    const float* Pptr = P + (size_t)b_row * N + bn + b_col;

    for (int k0 = 0; k0 < K; k0 += BK) {
        float4 av = *(const float4*)(Aptr + k0);
        As[a_col + 0][a_row] = av.x;
        As[a_col + 1][a_row] = av.y;
        As[a_col + 2][a_row] = av.z;
        As[a_col + 3][a_row] = av.w;
        float4 bv = *(const float4*)(Pptr + (size_t)k0 * N);
        *(float4*)&Bs[b_row][b_col] = bv;
        __syncthreads();

#pragma unroll
        for (int kk = 0; kk < BK; kk++) {
            float ar[8], br[8];
            *(float4*)&ar[0] = *(const float4*)&As[kk][ty * 4];
            *(float4*)&ar[4] = *(const float4*)&As[kk][64 + ty * 4];
            *(float4*)&br[0] = *(const float4*)&Bs[kk][tx * 4];
            *(float4*)&br[4] = *(const float4*)&Bs[kk][64 + tx * 4];
#pragma unroll
            for (int i = 0; i < 8; i++)
#pragma unroll
                for (int j = 0; j < 8; j++)
                    acc[i][j] += ar[i] * br[j];
        }
        __syncthreads();
    }

    // epilogue: rows {bm + ty*4 + i, bm + 64 + ty*4 + i}, cols {bn + tx*4 + j, bn + 64 + tx*4 + j}
#pragma unroll
    for (int i = 0; i < 8; i++) {
        int row = bm + ((i < 4) ? (ty * 4 + i) : (64 + ty * 4 + (i - 4)));
#pragma unroll
        for (int j = 0; j < 8; j++) {
            int col = bn + ((j < 4) ? (tx * 4 + j) : (64 + tx * 4 + (j - 4)));
            float bbv = (col < Nh) ? blo[col] : bhi[col - Nh];
            float v = tanhf(acc[i][j] + bbv);
            if (SCATTER) {
                // row m = t*64 + b  ->  out[b][t][col]
                int t = row >> 6;
                int bidx = row & 63;
                C[(size_t)bidx * (STEPS * ACTION_DIM) + t * ACTION_DIM + col] = v;
            } else {
                C[(size_t)row * N + col] = v;
            }
        }
    }
}

// ---------------- launch ----------------
extern "C" void kernel_launch(void* const* d_in, const int* in_sizes, int n_in,
                              void* d_out, int out_size) {
    const float* z     = (const float*)d_in[0];
    const float* omega = (const float*)d_in[1];
    const float* bpar  = (const float*)d_in[2];
    const float* W0r = (const float*)d_in[3];
    const float* W0i = (const float*)d_in[4];
    const float* b0r = (const float*)d_in[5];
    const float* b0i = (const float*)d_in[6];
    const float* W1r = (const float*)d_in[7];
    const float* W1i = (const float*)d_in[8];
    const float* b1r = (const float*)d_in[9];
    const float* b1i = (const float*)d_in[10];
    const float* W2r = (const float*)d_in[11];
    const float* W2i = (const float*)d_in[12];
    const float* b2r = (const float*)d_in[13];
    // d_in[14] = b2_im (unused: output keeps only the real part)

    float* out = (float*)d_out;                         // (64, 128, 256)
    float* out_z1 = out + (size_t)BATCH * STEPS * ACTION_DIM;  // (64, 1024)

    float *P0, *P1, *P2, *st, *a1, *a2;
    cudaGetSymbolAddress((void**)&P0, g_P0);
    cudaGetSymbolAddress((void**)&P1, g_P1);
    cudaGetSymbolAddress((void**)&P2, g_P2);
    cudaGetSymbolAddress((void**)&st, g_states);
    cudaGetSymbolAddress((void**)&a1, g_act1);
    cudaGetSymbolAddress((void**)&a2, g_act2);

    // pack structured weight matrices
    pack_full<<<(4 * 512 * 1024 + 255) / 256, 256>>>(W0r, W0i, P0, 512, 1024);
    pack_full<<<(4 * 1024 * 512 + 255) / 256, 256>>>(W1r, W1i, P1, 1024, 512);
    pack_half<<<(2 * 512 * 256 + 255) / 256, 256>>>(W2r, W2i, P2, 512, 256);

    // hopf chain: states z1..z128 + z1 to output tail
    hopf_kernel<<<(BATCH * UNITS + 255) / 256, 256>>>(z, omega, bpar, st, out_z1);

    // layer 0: (8192 x 1024) @ (1024 x 2048)
    {
        dim3 grid(2048 / BN, MROWS / BM);
        gemm_bias_tanh<false><<<grid, 256>>>(st, P0, b0r, b0i, 1024, a1, MROWS, 2048, 1024);
    }
    // layer 1: (8192 x 2048) @ (2048 x 1024)
    {
        dim3 grid(1024 / BN, MROWS / BM);
        gemm_bias_tanh<false><<<grid, 256>>>(a1, P1, b1r, b1i, 512, a2, MROWS, 1024, 2048);
    }
    // layer 2 (real half only) with scatter to (batch, step, action):
    {
        dim3 grid(256 / BN, MROWS / BM);
        gemm_bias_tanh<true><<<grid, 256>>>(a2, P2, b2r, b2r, 256, out, MROWS, 256, 1024);
    }
}

// round 3
// speedup vs baseline: 3.6034x; 3.6034x over previous
#include <cuda_runtime.h>
#include <math.h>
#include <cstdint>

#define DT 0.001f
#define STEPS 128
#define UNITS 512
#define BATCH 64
#define MROWS (STEPS * BATCH)   // 8192
#define ACTION_DIM 256

// ---------------- scratch ----------------
__device__ float g_states[MROWS * 1024];   // hopf states (tf32-rounded), row m = t*64+b
__device__ float g_act1[MROWS * 2048];     // layer0 out (tf32-rounded)
__device__ float g_act2[MROWS * 1024];     // layer1 out (tf32-rounded)
__device__ float g_P0[2048 * 1024];        // B^T layer0: [2N][2K]
__device__ float g_P1[1024 * 2048];
__device__ float g_P2[256 * 1024];

__device__ __forceinline__ float tf32r(float x) {
    float y; asm("cvt.rna.tf32.f32 %0, %1;" : "=f"(y) : "f"(x)); return y;
}
__device__ __forceinline__ uint32_t smem_u32(const void* p) {
    uint32_t a;
    asm("{ .reg .u64 t; cvta.to.shared.u64 t, %1; cvt.u32.u64 %0, t; }" : "=r"(a) : "l"(p));
    return a;
}
__device__ __forceinline__ void cp16(uint32_t s, const void* g) {
    asm volatile("cp.async.cg.shared.global [%0], [%1], 16;" :: "r"(s), "l"(g));
}

// ---------------- weight packing (tiled transpose, tf32-rounded) ----------------
__global__ void pack_full_T(const float* __restrict__ Wr, const float* __restrict__ Wi,
                            float* __restrict__ PT, int K, int N) {
    __shared__ float tile[32][33];
    int k0 = blockIdx.x * 32;
    int n0 = blockIdx.y * 32;
    int tx = threadIdx.x, ty0 = threadIdx.y;
#pragma unroll
    for (int i = 0; i < 4; i++) {
        int ty = ty0 + i * 8;
        int k = k0 + ty, n = n0 + tx;
        float v;
        if (k < K) v = (n < N) ? Wr[(size_t)k * N + n] : Wi[(size_t)k * N + n - N];
        else {
            int kk = k - K;
            v = (n < N) ? -Wi[(size_t)kk * N + n] : Wr[(size_t)kk * N + n - N];
        }
        tile[ty][tx] = tf32r(v);
    }
    __syncthreads();
#pragma unroll
    for (int i = 0; i < 4; i++) {
        int ty = ty0 + i * 8;
        PT[(size_t)(n0 + ty) * (2 * K) + k0 + tx] = tile[tx][ty];
    }
}
__global__ void pack_half_T(const float* __restrict__ Wr, const float* __restrict__ Wi,
                            float* __restrict__ PT, int K, int N) {
    __shared__ float tile[32][33];
    int k0 = blockIdx.x * 32;
    int n0 = blockIdx.y * 32;
    int tx = threadIdx.x, ty0 = threadIdx.y;
#pragma unroll
    for (int i = 0; i < 4; i++) {
        int ty = ty0 + i * 8;
        int k = k0 + ty, n = n0 + tx;
        float v = (k < K) ? Wr[(size_t)k * N + n] : -Wi[(size_t)(k - K) * N + n];
        tile[ty][tx] = tf32r(v);
    }
    __syncthreads();
#pragma unroll
    for (int i = 0; i < 4; i++) {
        int ty = ty0 + i * 8;
        PT[(size_t)(n0 + ty) * (2 * K) + k0 + tx] = tile[tx][ty];
    }
}

// ---------------- hopf chain ----------------
__global__ void hopf_kernel(const float* __restrict__ z0, const float* __restrict__ omega,
                            const float* __restrict__ bpar, float* __restrict__ states,
                            float* __restrict__ out_z1) {
    int tid = blockIdx.x * blockDim.x + threadIdx.x;
    if (tid >= BATCH * UNITS) return;
    int bi = tid / UNITS;
    int i  = tid - bi * UNITS;
    float x = z0[bi * 1024 + i];
    float y = z0[bi * 1024 + UNITS + i];
    float w = omega[bi] * (float)(i + 1);
    float bb = bpar[bi * UNITS + i];
#pragma unroll 4
    for (int t = 0; t < STEPS; t++) {
        float r2 = x * x + y * y;
        float g = bb - r2;
        float dx = g * x - w * y;
        float dy = g * y + w * x;
        x += DT * dx;
        y += DT * dy;
        float* row = states + ((size_t)(t * BATCH + bi)) * 1024;
        row[i] = tf32r(x);
        row[UNITS + i] = tf32r(y);
        if (t == 0) {
            out_z1[bi * 1024 + i] = x;           // full fp32 to output
            out_z1[bi * 1024 + UNITS + i] = y;
        }
    }
}

// ---------------- tf32 mma.sync GEMM + bias + tanh ----------------
// C[8192 x N2] = tanh(A[8192 x K2] @ BT[N2 x K2]^T + bias)
// CTA 128x128, BK=32, 8 warps (2m x 4n), warp tile 64x32 (4 m16-tiles x 4 n8-tiles).
#define BK 32
#define SSTRIDE 36                     // floats per smem row (pad 4)
#define STAGE_BYTES (128 * SSTRIDE * 4)  // 18432
#define SMEM_BYTES (4 * STAGE_BYTES)     // A0 A1 B0 B1 = 73728

__device__ __forceinline__ void mma_tf32(float* c, const uint32_t* a, const uint32_t* b) {
    asm volatile(
        "mma.sync.aligned.m16n8k8.row.col.f32.tf32.tf32.f32 "
        "{%0,%1,%2,%3}, {%4,%5,%6,%7}, {%8,%9}, {%0,%1,%2,%3};"
        : "+f"(c[0]), "+f"(c[1]), "+f"(c[2]), "+f"(c[3])
        : "r"(a[0]), "r"(a[1]), "r"(a[2]), "r"(a[3]), "r"(b[0]), "r"(b[1]));
}

template<bool SCATTER, bool CVTOUT>
__global__ __launch_bounds__(256, 2)
void gemm_mma(const float* __restrict__ A, const float* __restrict__ Bm,
              const float* __restrict__ blo, const float* __restrict__ bhi, int Nh,
              float* __restrict__ C, int K2, int N2) {
    extern __shared__ char sm[];
    const uint32_t smb = smem_u32(sm);
    const int tid = threadIdx.x;
    const int wid = tid >> 5, lane = tid & 31;
    const int wm = wid >> 2, wn = wid & 3;      // warp grid 2 x 4
    const int g = lane >> 2, t = lane & 3;

    const int bm = blockIdx.y * 128;
    const int bn = blockIdx.x * 128;
    const int nk = K2 / BK;

    // copy indexing: 256 threads, 4 passes cover 128 rows x 8 chunks of 16B
    const int row_c = tid >> 3;
    const int cq = tid & 7;
    const float* Agb = A  + (size_t)(bm + row_c) * K2 + cq * 4;
    const float* Bgb = Bm + (size_t)(bn + row_c) * K2 + cq * 4;
    const uint32_t sA = smb;
    const uint32_t sB = smb + 2 * STAGE_BYTES;
    const uint32_t s_off = row_c * (SSTRIDE * 4) + cq * 16;

    float acc[4][4][4];
#pragma unroll
    for (int mt = 0; mt < 4; mt++)
#pragma unroll
        for (int nt = 0; nt < 4; nt++)
#pragma unroll
            for (int r = 0; r < 4; r++) acc[mt][nt][r] = 0.0f;

    // prologue: stage 0
    {
#pragma unroll
        for (int p = 0; p < 4; p++) {
            cp16(sA + s_off + p * 32 * SSTRIDE * 4, Agb + (size_t)p * 32 * K2);
            cp16(sB + s_off + p * 32 * SSTRIDE * 4, Bgb + (size_t)p * 32 * K2);
        }
        asm volatile("cp.async.commit_group;" ::: "memory");
    }

    const int a_base = (wm * 64 + g) * SSTRIDE;
    const int b_base = (wn * 32 + g) * SSTRIDE;

    for (int c = 0; c < nk; c++) {
        const int buf = c & 1;
        if (c + 1 < nk) {
            const int nbuf = buf ^ 1;
            const float* Ag = Agb + (c + 1) * BK;
            const float* Bg = Bgb + (c + 1) * BK;
#pragma unroll
            for (int p = 0; p < 4; p++) {
                cp16(sA + nbuf * STAGE_BYTES + s_off + p * 32 * SSTRIDE * 4,
                     Ag + (size_t)p * 32 * K2);
                cp16(sB + nbuf * STAGE_BYTES + s_off + p * 32 * SSTRIDE * 4,
                     Bg + (size_t)p * 32 * K2);
            }
            asm volatile("cp.async.commit_group;" ::: "memory");
            asm volatile("cp.async.wait_group 1;" ::: "memory");
        } else {
            asm volatile("cp.async.wait_group 0;" ::: "memory");
        }
        __syncthreads();

        const uint32_t* As = (const uint32_t*)(sm + buf * STAGE_BYTES);
        const uint32_t* Bs = (const uint32_t*)(sm + 2 * STAGE_BYTES + buf * STAGE_BYTES);

#pragma unroll
        for (int ks = 0; ks < 4; ks++) {
            uint32_t af[4][4], bf[4][2];
#pragma unroll
            for (int mt = 0; mt < 4; mt++) {
                int idx = a_base + mt * 16 * SSTRIDE + ks * 8 + t;
                af[mt][0] = As[idx];
                af[mt][1] = As[idx + 8 * SSTRIDE];
                af[mt][2] = As[idx + 4];
                af[mt][3] = As[idx + 8 * SSTRIDE + 4];
            }
#pragma unroll
            for (int nt = 0; nt < 4; nt++) {
                int idx = b_base + nt * 8 * SSTRIDE + ks * 8 + t;
                bf[nt][0] = Bs[idx];
                bf[nt][1] = Bs[idx + 4];
            }
#pragma unroll
            for (int mt = 0; mt < 4; mt++)
#pragma unroll
                for (int nt = 0; nt < 4; nt++)
                    mma_tf32(acc[mt][nt], af[mt], bf[nt]);
        }
        __syncthreads();
    }

    // epilogue: bias + tanh + store (float2 per fragment row)
#pragma unroll
    for (int mt = 0; mt < 4; mt++) {
        int row0 = bm + wm * 64 + mt * 16 + g;
#pragma unroll
        for (int nt = 0; nt < 4; nt++) {
            int cn = bn + wn * 32 + nt * 8 + 2 * t;
            float bv0 = (cn < Nh) ? blo[cn] : bhi[cn - Nh];
            float bv1 = (cn + 1 < Nh) ? blo[cn + 1] : bhi[cn + 1 - Nh];
            float v0 = tanhf(acc[mt][nt][0] + bv0);
            float v1 = tanhf(acc[mt][nt][1] + bv1);
            float v2 = tanhf(acc[mt][nt][2] + bv0);
            float v3 = tanhf(acc[mt][nt][3] + bv1);
            if (CVTOUT) { v0 = tf32r(v0); v1 = tf32r(v1); v2 = tf32r(v2); v3 = tf32r(v3); }
            float* d0;
            float* d1;
            if (SCATTER) {
                int t0 = row0 >> 6, b0i = row0 & 63;
                int r1 = row0 + 8;
                int t1 = r1 >> 6, b1i = r1 & 63;
                d0 = C + (size_t)b0i * (STEPS * ACTION_DIM) + t0 * ACTION_DIM + cn;
                d1 = C + (size_t)b1i * (STEPS * ACTION_DIM) + t1 * ACTION_DIM + cn;
            } else {
                d0 = C + (size_t)row0 * N2 + cn;
                d1 = C + (size_t)(row0 + 8) * N2 + cn;
            }
            *(float2*)d0 = make_float2(v0, v1);
            *(float2*)d1 = make_float2(v2, v3);
        }
    }
}

// ---------------- launch ----------------
extern "C" void kernel_launch(void* const* d_in, const int* in_sizes, int n_in,
                              void* d_out, int out_size) {
    const float* z     = (const float*)d_in[0];
    const float* omega = (const float*)d_in[1];
    const float* bpar  = (const float*)d_in[2];
    const float* W0r = (const float*)d_in[3];
    const float* W0i = (const float*)d_in[4];
    const float* b0r = (const float*)d_in[5];
    const float* b0i = (const float*)d_in[6];
    const float* W1r = (const float*)d_in[7];
    const float* W1i = (const float*)d_in[8];
    const float* b1r = (const float*)d_in[9];
    const float* b1i = (const float*)d_in[10];
    const float* W2r = (const float*)d_in[11];
    const float* W2i = (const float*)d_in[12];
    const float* b2r = (const float*)d_in[13];

    float* out = (float*)d_out;                                 // (64, 128, 256)
    float* out_z1 = out + (size_t)BATCH * STEPS * ACTION_DIM;   // (64, 1024)

    float *P0, *P1, *P2, *st, *a1, *a2;
    cudaGetSymbolAddress((void**)&P0, g_P0);
    cudaGetSymbolAddress((void**)&P1, g_P1);
    cudaGetSymbolAddress((void**)&P2, g_P2);
    cudaGetSymbolAddress((void**)&st, g_states);
    cudaGetSymbolAddress((void**)&a1, g_act1);
    cudaGetSymbolAddress((void**)&a2, g_act2);

    cudaFuncSetAttribute(gemm_mma<false, true>,
                         cudaFuncAttributeMaxDynamicSharedMemorySize, SMEM_BYTES);
    cudaFuncSetAttribute(gemm_mma<true, false>,
                         cudaFuncAttributeMaxDynamicSharedMemorySize, SMEM_BYTES);

    {
        dim3 blk(32, 8);
        pack_full_T<<<dim3(1024 / 32, 2048 / 32), blk>>>(W0r, W0i, P0, 512, 1024);
        pack_full_T<<<dim3(2048 / 32, 1024 / 32), blk>>>(W1r, W1i, P1, 1024, 512);
        pack_half_T<<<dim3(1024 / 32,  256 / 32), blk>>>(W2r, W2i, P2, 512, 256);
    }

    hopf_kernel<<<(BATCH * UNITS + 255) / 256, 256>>>(z, omega, bpar, st, out_z1);

    // layer 0: (8192 x 1024) @ (1024 x 2048)
    gemm_mma<false, true><<<dim3(2048 / 128, MROWS / 128), 256, SMEM_BYTES>>>(
        st, P0, b0r, b0i, 1024, a1, 1024, 2048);
    // layer 1: (8192 x 2048) @ (2048 x 1024)
    gemm_mma<false, true><<<dim3(1024 / 128, MROWS / 128), 256, SMEM_BYTES>>>(
        a1, P1, b1r, b1i, 512, a2, 2048, 1024);
    // layer 2: (8192 x 1024) @ (1024 x 256), scatter to (batch, step, action)
    gemm_mma<true, false><<<dim3(256 / 128, MROWS / 128), 256, SMEM_BYTES>>>(
        a2, P2, b2r, b2r, 256, out, 1024, 256);
}

// round 4
// speedup vs baseline: 6.1685x; 1.7119x over previous
#include <cuda_runtime.h>
#include <cuda_fp16.h>
#include <math.h>
#include <cstdint>

#define DT 0.001f
#define STEPS 128
#define UNITS 512
#define BATCH 64
#define MROWS (STEPS * BATCH)   // 8192
#define ACTION_DIM 256

// ---------------- scratch ----------------
__device__ __half g_states_h[MROWS * 1024];  // hopf states (fp16), row m = t*64+b
__device__ __half g_act1_h[MROWS * 2048];
__device__ __half g_act2_h[MROWS * 1024];
__device__ __half g_P0h[2048 * 1024];        // B^T layer0: [2N][2K] fp16
__device__ __half g_P1h[1024 * 2048];
__device__ __half g_P2h[256 * 1024];

__device__ __forceinline__ uint32_t smem_u32(const void* p) {
    uint32_t a;
    asm("{ .reg .u64 t; cvta.to.shared.u64 t, %1; cvt.u32.u64 %0, t; }" : "=r"(a) : "l"(p));
    return a;
}
__device__ __forceinline__ void cp16(uint32_t s, const void* g) {
    asm volatile("cp.async.cg.shared.global [%0], [%1], 16;" :: "r"(s), "l"(g));
}
__device__ __forceinline__ void ldm_x4(uint32_t* r, uint32_t addr) {
    asm volatile("ldmatrix.sync.aligned.m8n8.x4.shared.b16 {%0,%1,%2,%3}, [%4];"
                 : "=r"(r[0]), "=r"(r[1]), "=r"(r[2]), "=r"(r[3]) : "r"(addr));
}
__device__ __forceinline__ void mma_f16(float* c, const uint32_t* a, const uint32_t* b) {
    asm volatile(
        "mma.sync.aligned.m16n8k16.row.col.f32.f16.f16.f32 "
        "{%0,%1,%2,%3}, {%4,%5,%6,%7}, {%8,%9}, {%0,%1,%2,%3};"
        : "+f"(c[0]), "+f"(c[1]), "+f"(c[2]), "+f"(c[3])
        : "r"(a[0]), "r"(a[1]), "r"(a[2]), "r"(a[3]), "r"(b[0]), "r"(b[1]));
}

// ---------------- weight packing (tiled transpose -> fp16) ----------------
__global__ void pack_full_T(const float* __restrict__ Wr, const float* __restrict__ Wi,
                            __half* __restrict__ PT, int K, int N) {
    __shared__ float tile[32][33];
    int k0 = blockIdx.x * 32;
    int n0 = blockIdx.y * 32;
    int tx = threadIdx.x, ty0 = threadIdx.y;
#pragma unroll
    for (int i = 0; i < 4; i++) {
        int ty = ty0 + i * 8;
        int k = k0 + ty, n = n0 + tx;
        float v;
        if (k < K) v = (n < N) ? Wr[(size_t)k * N + n] : Wi[(size_t)k * N + n - N];
        else {
            int kk = k - K;
            v = (n < N) ? -Wi[(size_t)kk * N + n] : Wr[(size_t)kk * N + n - N];
        }
        tile[ty][tx] = v;
    }
    __syncthreads();
#pragma unroll
    for (int i = 0; i < 4; i++) {
        int ty = ty0 + i * 8;
        PT[(size_t)(n0 + ty) * (2 * K) + k0 + tx] = __float2half_rn(tile[tx][ty]);
    }
}
__global__ void pack_half_T(const float* __restrict__ Wr, const float* __restrict__ Wi,
                            __half* __restrict__ PT, int K, int N) {
    __shared__ float tile[32][33];
    int k0 = blockIdx.x * 32;
    int n0 = blockIdx.y * 32;
    int tx = threadIdx.x, ty0 = threadIdx.y;
#pragma unroll
    for (int i = 0; i < 4; i++) {
        int ty = ty0 + i * 8;
        int k = k0 + ty, n = n0 + tx;
        float v = (k < K) ? Wr[(size_t)k * N + n] : -Wi[(size_t)(k - K) * N + n];
        tile[ty][tx] = v;
    }
    __syncthreads();
#pragma unroll
    for (int i = 0; i < 4; i++) {
        int ty = ty0 + i * 8;
        PT[(size_t)(n0 + ty) * (2 * K) + k0 + tx] = __float2half_rn(tile[tx][ty]);
    }
}

// ---------------- hopf chain ----------------
__global__ void hopf_kernel(const float* __restrict__ z0, const float* __restrict__ omega,
                            const float* __restrict__ bpar, __half* __restrict__ states,
                            float* __restrict__ out_z1) {
    int tid = blockIdx.x * blockDim.x + threadIdx.x;
    if (tid >= BATCH * UNITS) return;
    int bi = tid / UNITS;
    int i  = tid - bi * UNITS;
    float x = z0[bi * 1024 + i];
    float y = z0[bi * 1024 + UNITS + i];
    float w = omega[bi] * (float)(i + 1);
    float bb = bpar[bi * UNITS + i];
#pragma unroll 4
    for (int t = 0; t < STEPS; t++) {
        float r2 = x * x + y * y;
        float g = bb - r2;
        float dx = g * x - w * y;
        float dy = g * y + w * x;
        x += DT * dx;
        y += DT * dy;
        __half* row = states + ((size_t)(t * BATCH + bi)) * 1024;
        row[i] = __float2half_rn(x);
        row[UNITS + i] = __float2half_rn(y);
        if (t == 0) {
            out_z1[bi * 1024 + i] = x;
            out_z1[bi * 1024 + UNITS + i] = y;
        }
    }
}

// ---------------- fp16 mma.sync GEMM + bias + tanh ----------------
// C[8192 x N2] = tanh(A[8192 x K] @ Bw[N2 x K]^T + bias)
// CTA 128 x NT. 8 warps 2x4. Warp tile 64 x (NT/4). BK=64 halves (4 k16 steps).
// 3-stage cp.async. Rows are 128B in smem with XOR-16B swizzle (conflict-free).
#define NSTAGE 3

template<int NT, bool SCATTER>
__global__ __launch_bounds__(256, NT == 128 ? 2 : 1)
void gemm_h(const __half* __restrict__ A, const __half* __restrict__ Bw,
            const float* __restrict__ blo, const float* __restrict__ bhi, int Nh,
            void* __restrict__ Cout, int K, int N2) {
    constexpr int NTN = NT / 32;                  // 8x-col n-tiles per warp
    constexpr int SBYTES_A = 128 * 128;
    constexpr int STAGE = SBYTES_A + NT * 128;
    extern __shared__ char sm[];
    const uint32_t smb = smem_u32(sm);

    const int tid = threadIdx.x;
    const int wid = tid >> 5, lane = tid & 31;
    const int wm = wid >> 2, wn = wid & 3;
    const int g = lane >> 2, tq = lane & 3;

    const int bm = blockIdx.y * 128;
    const int bn = blockIdx.x * NT;
    const int nk = K / 64;

    // copy indexing: thread -> (row base r0, 16B slot s); swizzled slot fixed per thread
    const int cr0 = tid >> 3;
    const int cs = tid & 7;
    const uint32_t cswz = (uint32_t)((cs ^ (cr0 & 7)) << 4);
    const __half* Agb = A  + (size_t)(bm + cr0) * K + cs * 8;
    const __half* Bgb = Bw + (size_t)(bn + cr0) * K + cs * 8;

    float acc[4][NTN][4];
#pragma unroll
    for (int mt = 0; mt < 4; mt++)
#pragma unroll
        for (int nt = 0; nt < NTN; nt++)
#pragma unroll
            for (int r = 0; r < 4; r++) acc[mt][nt][r] = 0.0f;

    auto issue = [&](int buf, int ch) {
        uint32_t sa = smb + buf * STAGE;
        uint32_t sb = sa + SBYTES_A;
        const __half* Ac = Agb + ch * 64;
        const __half* Bc = Bgb + ch * 64;
#pragma unroll
        for (int it = 0; it < 4; it++)
            cp16(sa + (uint32_t)(cr0 + it * 32) * 128 + cswz, Ac + (size_t)it * 32 * K);
#pragma unroll
        for (int it = 0; it < NT / 32; it++)
            cp16(sb + (uint32_t)(cr0 + it * 32) * 128 + cswz, Bc + (size_t)it * 32 * K);
        asm volatile("cp.async.commit_group;" ::: "memory");
    };

    issue(0, 0);
    issue(1, 1);

    // fragment addressing
    const int lm = lane & 15;
    const int l16 = lane >> 4;
    const int fx = lane & 7;                      // row&7 for swizzle
    const uint32_t a_rowoff = (uint32_t)(wm * 64 + lm) * 128;
    const uint32_t b_rowoff = (uint32_t)(wn * (NTN * 8) + lm) * 128;

    for (int c = 0; c < nk; c++) {
        asm volatile("cp.async.wait_group 1;" ::: "memory");
        __syncthreads();
        if (c + 2 < nk) issue((c + 2) % NSTAGE, c + 2);
        else asm volatile("cp.async.commit_group;" ::: "memory");

        const int buf = c % NSTAGE;
        const uint32_t sa = smb + buf * STAGE;
        const uint32_t sb = sa + SBYTES_A;

#pragma unroll
        for (int ks = 0; ks < 4; ks++) {
            const uint32_t kslot = (uint32_t)(((ks * 2 + l16) ^ fx) << 4);
            uint32_t af[4][4];
#pragma unroll
            for (int mt = 0; mt < 4; mt++)
                ldm_x4(af[mt], sa + a_rowoff + (uint32_t)(mt * 16) * 128 + kslot);
            uint32_t bf[NTN][2];
#pragma unroll
            for (int p = 0; p < NTN / 2; p++) {
                uint32_t r[4];
                ldm_x4(r, sb + b_rowoff + (uint32_t)(p * 16) * 128 + kslot);
                bf[2 * p][0] = r[0]; bf[2 * p + 1][0] = r[1];
                bf[2 * p][1] = r[2]; bf[2 * p + 1][1] = r[3];
            }
#pragma unroll
            for (int mt = 0; mt < 4; mt++)
#pragma unroll
                for (int nt = 0; nt < NTN; nt++)
                    mma_f16(acc[mt][nt], af[mt], bf[nt]);
        }
    }

    // epilogue: bias + tanh
#pragma unroll
    for (int mt = 0; mt < 4; mt++) {
        const int row0 = bm + wm * 64 + mt * 16 + g;
#pragma unroll
        for (int nt = 0; nt < NTN; nt++) {
            const int col = bn + wn * (NTN * 8) + nt * 8 + 2 * tq;
            const float bv0 = (col < Nh) ? blo[col] : bhi[col - Nh];
            const float bv1 = (col + 1 < Nh) ? blo[col + 1] : bhi[col + 1 - Nh];
            const float v0 = tanhf(acc[mt][nt][0] + bv0);
            const float v1 = tanhf(acc[mt][nt][1] + bv1);
            const float v2 = tanhf(acc[mt][nt][2] + bv0);
            const float v3 = tanhf(acc[mt][nt][3] + bv1);
            if (SCATTER) {
                float* C = (float*)Cout;
                const int t0 = row0 >> 6, b0 = row0 & 63;
                const int r1 = row0 + 8;
                const int t1 = r1 >> 6, b1 = r1 & 63;
                *(float2*)(C + (size_t)b0 * (STEPS * ACTION_DIM) + t0 * ACTION_DIM + col) =
                    make_float2(v0, v1);
                *(float2*)(C + (size_t)b1 * (STEPS * ACTION_DIM) + t1 * ACTION_DIM + col) =
                    make_float2(v2, v3);
            } else {
                __half* C = (__half*)Cout;
                *(__half2*)(C + (size_t)row0 * N2 + col) = __floats2half2_rn(v0, v1);
                *(__half2*)(C + (size_t)(row0 + 8) * N2 + col) = __floats2half2_rn(v2, v3);
            }
        }
    }
}

// ---------------- launch ----------------
extern "C" void kernel_launch(void* const* d_in, const int* in_sizes, int n_in,
                              void* d_out, int out_size) {
    const float* z     = (const float*)d_in[0];
    const float* omega = (const float*)d_in[1];
    const float* bpar  = (const float*)d_in[2];
    const float* W0r = (const float*)d_in[3];
    const float* W0i = (const float*)d_in[4];
    const float* b0r = (const float*)d_in[5];
    const float* b0i = (const float*)d_in[6];
    const float* W1r = (const float*)d_in[7];
    const float* W1i = (const float*)d_in[8];
    const float* b1r = (const float*)d_in[9];
    const float* b1i = (const float*)d_in[10];
    const float* W2r = (const float*)d_in[11];
    const float* W2i = (const float*)d_in[12];
    const float* b2r = (const float*)d_in[13];

    float* out = (float*)d_out;                                 // (64, 128, 256)
    float* out_z1 = out + (size_t)BATCH * STEPS * ACTION_DIM;   // (64, 1024)

    __half *P0, *P1, *P2, *st, *a1, *a2;
    cudaGetSymbolAddress((void**)&P0, g_P0h);
    cudaGetSymbolAddress((void**)&P1, g_P1h);
    cudaGetSymbolAddress((void**)&P2, g_P2h);
    cudaGetSymbolAddress((void**)&st, g_states_h);
    cudaGetSymbolAddress((void**)&a1, g_act1_h);
    cudaGetSymbolAddress((void**)&a2, g_act2_h);

    constexpr int SM256 = NSTAGE * (128 * 128 + 256 * 128);   // 147456
    constexpr int SM128 = NSTAGE * (128 * 128 + 128 * 128);   // 98304
    cudaFuncSetAttribute(gemm_h<256, false>,
                         cudaFuncAttributeMaxDynamicSharedMemorySize, SM256);
    cudaFuncSetAttribute(gemm_h<128, true>,
                         cudaFuncAttributeMaxDynamicSharedMemorySize, SM128);

    {
        dim3 blk(32, 8);
        pack_full_T<<<dim3(1024 / 32, 2048 / 32), blk>>>(W0r, W0i, P0, 512, 1024);
        pack_full_T<<<dim3(2048 / 32, 1024 / 32), blk>>>(W1r, W1i, P1, 1024, 512);
        pack_half_T<<<dim3(1024 / 32,  256 / 32), blk>>>(W2r, W2i, P2, 512, 256);
    }

    hopf_kernel<<<(BATCH * UNITS + 255) / 256, 256>>>(z, omega, bpar, st, out_z1);

    // layer 0: (8192 x 1024) @ (1024 x 2048)
    gemm_h<256, false><<<dim3(2048 / 256, MROWS / 128), 256, SM256>>>(
        st, P0, b0r, b0i, 1024, a1, 1024, 2048);
    // layer 1: (8192 x 2048) @ (2048 x 1024)
    gemm_h<256, false><<<dim3(1024 / 256, MROWS / 128), 256, SM256>>>(
        a1, P1, b1r, b1i, 512, a2, 2048, 1024);
    // layer 2: (8192 x 1024) @ (1024 x 256) -> scatter (batch, step, action)
    gemm_h<128, true><<<dim3(256 / 128, MROWS / 128), 256, SM128>>>(
        a2, P2, b2r, b2r, 256, out, 1024, 256);
}

// round 5
// speedup vs baseline: 6.3287x; 1.0260x over previous
#include <cuda_runtime.h>
#include <cuda_fp16.h>
#include <math.h>
#include <cstdint>

#define DT 0.001f
#define STEPS 128
#define UNITS 512
#define BATCH 64
#define MROWS (STEPS * BATCH)   // 8192
#define ACTION_DIM 256

// ---------------- scratch ----------------
__device__ __half g_states_h[MROWS * 1024];
__device__ __half g_act1_h[MROWS * 2048];
__device__ __half g_act2_h[MROWS * 1024];
__device__ __half g_P0h[2048 * 1024];
__device__ __half g_P1h[1024 * 2048];
__device__ __half g_P2h[256 * 1024];

__device__ __forceinline__ uint32_t smem_u32(const void* p) {
    uint32_t a;
    asm("{ .reg .u64 t; cvta.to.shared.u64 t, %1; cvt.u32.u64 %0, t; }" : "=r"(a) : "l"(p));
    return a;
}
__device__ __forceinline__ void cp16(uint32_t s, const void* g) {
    asm volatile("cp.async.cg.shared.global [%0], [%1], 16;" :: "r"(s), "l"(g));
}
__device__ __forceinline__ void ldm_x4(uint32_t* r, uint32_t addr) {
    asm volatile("ldmatrix.sync.aligned.m8n8.x4.shared.b16 {%0,%1,%2,%3}, [%4];"
                 : "=r"(r[0]), "=r"(r[1]), "=r"(r[2]), "=r"(r[3]) : "r"(addr));
}
__device__ __forceinline__ void mma_f16(float* c, const uint32_t* a, const uint32_t* b) {
    asm volatile(
        "mma.sync.aligned.m16n8k16.row.col.f32.f16.f16.f32 "
        "{%0,%1,%2,%3}, {%4,%5,%6,%7}, {%8,%9}, {%0,%1,%2,%3};"
        : "+f"(c[0]), "+f"(c[1]), "+f"(c[2]), "+f"(c[3])
        : "r"(a[0]), "r"(a[1]), "r"(a[2]), "r"(a[3]), "r"(b[0]), "r"(b[1]));
}

// ---------------- weight packing (tiled transpose -> fp16) ----------------
__global__ void pack_full_T(const float* __restrict__ Wr, const float* __restrict__ Wi,
                            __half* __restrict__ PT, int K, int N) {
    __shared__ float tile[32][33];
    int k0 = blockIdx.x * 32;
    int n0 = blockIdx.y * 32;
    int tx = threadIdx.x, ty0 = threadIdx.y;
#pragma unroll
    for (int i = 0; i < 4; i++) {
        int ty = ty0 + i * 8;
        int k = k0 + ty, n = n0 + tx;
        float v;
        if (k < K) v = (n < N) ? Wr[(size_t)k * N + n] : Wi[(size_t)k * N + n - N];
        else {
            int kk = k - K;
            v = (n < N) ? -Wi[(size_t)kk * N + n] : Wr[(size_t)kk * N + n - N];
        }
        tile[ty][tx] = v;
    }
    __syncthreads();
#pragma unroll
    for (int i = 0; i < 4; i++) {
        int ty = ty0 + i * 8;
        PT[(size_t)(n0 + ty) * (2 * K) + k0 + tx] = __float2half_rn(tile[tx][ty]);
    }
}
__global__ void pack_half_T(const float* __restrict__ Wr, const float* __restrict__ Wi,
                            __half* __restrict__ PT, int K, int N) {
    __shared__ float tile[32][33];
    int k0 = blockIdx.x * 32;
    int n0 = blockIdx.y * 32;
    int tx = threadIdx.x, ty0 = threadIdx.y;
#pragma unroll
    for (int i = 0; i < 4; i++) {
        int ty = ty0 + i * 8;
        int k = k0 + ty, n = n0 + tx;
        float v = (k < K) ? Wr[(size_t)k * N + n] : -Wi[(size_t)(k - K) * N + n];
        tile[ty][tx] = v;
    }
    __syncthreads();
#pragma unroll
    for (int i = 0; i < 4; i++) {
        int ty = ty0 + i * 8;
        PT[(size_t)(n0 + ty) * (2 * K) + k0 + tx] = __float2half_rn(tile[tx][ty]);
    }
}

// ---------------- hopf chain ----------------
__global__ void hopf_kernel(const float* __restrict__ z0, const float* __restrict__ omega,
                            const float* __restrict__ bpar, __half* __restrict__ states,
                            float* __restrict__ out_z1) {
    int tid = blockIdx.x * blockDim.x + threadIdx.x;
    if (tid >= BATCH * UNITS) return;
    int bi = tid / UNITS;
    int i  = tid - bi * UNITS;
    float x = z0[bi * 1024 + i];
    float y = z0[bi * 1024 + UNITS + i];
    float w = omega[bi] * (float)(i + 1);
    float bb = bpar[bi * UNITS + i];
#pragma unroll 4
    for (int t = 0; t < STEPS; t++) {
        float r2 = x * x + y * y;
        float g = bb - r2;
        float dx = g * x - w * y;
        float dy = g * y + w * x;
        x += DT * dx;
        y += DT * dy;
        __half* row = states + ((size_t)(t * BATCH + bi)) * 1024;
        row[i] = __float2half_rn(x);
        row[UNITS + i] = __float2half_rn(y);
        if (t == 0) {
            out_z1[bi * 1024 + i] = x;
            out_z1[bi * 1024 + UNITS + i] = y;
        }
    }
}

// ---------------- fp16 mma.sync GEMM + bias + tanh ----------------
// C[8192 x N2] = tanh(A[8192 x K] @ Bw[N2 x K]^T + bias)
// CTA 128 x NT, 8 warps 2x4, warp tile 64 x (NT/4).
// K processed in PAIRS of 64-half chunks (128 halves per barrier), 2 pairs
// double-buffered in smem; ldmatrix fragments double-buffered across the
// 8 k16-steps of a pair (including the intra-pair chunk boundary).
template<int NT, bool SCATTER>
__global__ __launch_bounds__(256, 1)
void gemm_h(const __half* __restrict__ A, const __half* __restrict__ Bw,
            const float* __restrict__ blo, const float* __restrict__ bhi, int Nh,
            void* __restrict__ Cout, int K, int N2) {
    constexpr int NTN = NT / 32;
    constexpr int CH_A = 128 * 128;          // bytes of A per 64-half chunk
    constexpr int CHUNK = CH_A + NT * 128;   // A + B per chunk
    constexpr int PAIR = 2 * CHUNK;
    extern __shared__ char sm[];
    const uint32_t smb = smem_u32(sm);

    const int tid = threadIdx.x;
    const int wid = tid >> 5, lane = tid & 31;
    const int wm = wid >> 2, wn = wid & 3;
    const int g = lane >> 2, tq = lane & 3;

    const int bm = blockIdx.y * 128;
    const int bn = blockIdx.x * NT;
    const int nk2 = K / 128;                 // number of pairs

    // copy indexing
    const int cr0 = tid >> 3;
    const int cs = tid & 7;
    const uint32_t cswz = (uint32_t)((cs ^ (cr0 & 7)) << 4);
    const __half* Agb = A  + (size_t)(bm + cr0) * K + cs * 8;
    const __half* Bgb = Bw + (size_t)(bn + cr0) * K + cs * 8;

    float acc[4][NTN][4];
#pragma unroll
    for (int mt = 0; mt < 4; mt++)
#pragma unroll
        for (int nt = 0; nt < NTN; nt++)
#pragma unroll
            for (int r = 0; r < 4; r++) acc[mt][nt][r] = 0.0f;

    auto issue_pair = [&](int p) {
        const uint32_t base = smb + (uint32_t)(p & 1) * PAIR;
#pragma unroll
        for (int sub = 0; sub < 2; sub++) {
            const uint32_t sa = base + sub * CHUNK;
            const uint32_t sb = sa + CH_A;
            const __half* Ac = Agb + (2 * p + sub) * 64;
            const __half* Bc = Bgb + (2 * p + sub) * 64;
#pragma unroll
            for (int it = 0; it < 4; it++)
                cp16(sa + (uint32_t)(cr0 + it * 32) * 128 + cswz, Ac + (size_t)it * 32 * K);
#pragma unroll
            for (int it = 0; it < NT / 32; it++)
                cp16(sb + (uint32_t)(cr0 + it * 32) * 128 + cswz, Bc + (size_t)it * 32 * K);
        }
        asm volatile("cp.async.commit_group;" ::: "memory");
    };

    // fragment addressing
    const int lm = lane & 15;
    const int l16 = lane >> 4;
    const int fx = lane & 7;
    const uint32_t a_rowoff = (uint32_t)(wm * 64 + lm) * 128;
    const uint32_t b_rowoff = (uint32_t)(wn * (NTN * 8) + lm) * 128;

    uint32_t af[2][4][4];
    uint32_t bf[2][NTN][2];

    auto loadF = [&](int set, uint32_t pbase, int kk) {
        const uint32_t cb = pbase + (uint32_t)(kk >> 2) * CHUNK;
        const int ks = kk & 3;
        const uint32_t kslot = (uint32_t)(((ks * 2 + l16) ^ fx) << 4);
        const uint32_t sa = cb + a_rowoff + kslot;
        const uint32_t sb = cb + CH_A + b_rowoff + kslot;
#pragma unroll
        for (int mt = 0; mt < 4; mt++)
            ldm_x4(af[set][mt], sa + (uint32_t)(mt * 16) * 128);
#pragma unroll
        for (int p = 0; p < NTN / 2; p++) {
            uint32_t r[4];
            ldm_x4(r, sb + (uint32_t)(p * 16) * 128);
            bf[set][2 * p][0] = r[0]; bf[set][2 * p + 1][0] = r[1];
            bf[set][2 * p][1] = r[2]; bf[set][2 * p + 1][1] = r[3];
        }
    };

    issue_pair(0);

    for (int c2 = 0; c2 < nk2; c2++) {
        asm volatile("cp.async.wait_group 0;" ::: "memory");
        __syncthreads();
        const uint32_t pbase = smb + (uint32_t)(c2 & 1) * PAIR;

        loadF(0, pbase, 0);
        if (c2 + 1 < nk2) issue_pair(c2 + 1);

#pragma unroll
        for (int kk = 0; kk < 8; kk++) {
            if (kk < 7) loadF((kk + 1) & 1, pbase, kk + 1);
            const int s = kk & 1;
#pragma unroll
            for (int mt = 0; mt < 4; mt++)
#pragma unroll
                for (int nt = 0; nt < NTN; nt++)
                    mma_f16(acc[mt][nt], af[s][mt], bf[s][nt]);
        }
        __syncthreads();
    }

    // epilogue: bias + tanh
#pragma unroll
    for (int mt = 0; mt < 4; mt++) {
        const int row0 = bm + wm * 64 + mt * 16 + g;
#pragma unroll
        for (int nt = 0; nt < NTN; nt++) {
            const int col = bn + wn * (NTN * 8) + nt * 8 + 2 * tq;
            const float bv0 = (col < Nh) ? blo[col] : bhi[col - Nh];
            const float bv1 = (col + 1 < Nh) ? blo[col + 1] : bhi[col + 1 - Nh];
            const float v0 = tanhf(acc[mt][nt][0] + bv0);
            const float v1 = tanhf(acc[mt][nt][1] + bv1);
            const float v2 = tanhf(acc[mt][nt][2] + bv0);
            const float v3 = tanhf(acc[mt][nt][3] + bv1);
            if (SCATTER) {
                float* C = (float*)Cout;
                const int t0 = row0 >> 6, b0 = row0 & 63;
                const int r1 = row0 + 8;
                const int t1 = r1 >> 6, b1 = r1 & 63;
                *(float2*)(C + (size_t)b0 * (STEPS * ACTION_DIM) + t0 * ACTION_DIM + col) =
                    make_float2(v0, v1);
                *(float2*)(C + (size_t)b1 * (STEPS * ACTION_DIM) + t1 * ACTION_DIM + col) =
                    make_float2(v2, v3);
            } else {
                __half* C = (__half*)Cout;
                *(__half2*)(C + (size_t)row0 * N2 + col) = __floats2half2_rn(v0, v1);
                *(__half2*)(C + (size_t)(row0 + 8) * N2 + col) = __floats2half2_rn(v2, v3);
            }
        }
    }
}

// ---------------- launch ----------------
extern "C" void kernel_launch(void* const* d_in, const int* in_sizes, int n_in,
                              void* d_out, int out_size) {
    const float* z     = (const float*)d_in[0];
    const float* omega = (const float*)d_in[1];
    const float* bpar  = (const float*)d_in[2];
    const float* W0r = (const float*)d_in[3];
    const float* W0i = (const float*)d_in[4];
    const float* b0r = (const float*)d_in[5];
    const float* b0i = (const float*)d_in[6];
    const float* W1r = (const float*)d_in[7];
    const float* W1i = (const float*)d_in[8];
    const float* b1r = (const float*)d_in[9];
    const float* b1i = (const float*)d_in[10];
    const float* W2r = (const float*)d_in[11];
    const float* W2i = (const float*)d_in[12];
    const float* b2r = (const float*)d_in[13];

    float* out = (float*)d_out;                                 // (64, 128, 256)
    float* out_z1 = out + (size_t)BATCH * STEPS * ACTION_DIM;   // (64, 1024)

    __half *P0, *P1, *P2, *st, *a1, *a2;
    cudaGetSymbolAddress((void**)&P0, g_P0h);
    cudaGetSymbolAddress((void**)&P1, g_P1h);
    cudaGetSymbolAddress((void**)&P2, g_P2h);
    cudaGetSymbolAddress((void**)&st, g_states_h);
    cudaGetSymbolAddress((void**)&a1, g_act1_h);
    cudaGetSymbolAddress((void**)&a2, g_act2_h);

    constexpr int SM256 = 2 * 2 * (128 * 128 + 256 * 128);   // 196608 -> 192KB
    constexpr int SM128 = 2 * 2 * (128 * 128 + 128 * 128);   // 131072 -> 128KB
    cudaFuncSetAttribute(gemm_h<256, false>,
                         cudaFuncAttributeMaxDynamicSharedMemorySize, SM256);
    cudaFuncSetAttribute(gemm_h<128, true>,
                         cudaFuncAttributeMaxDynamicSharedMemorySize, SM128);

    {
        dim3 blk(32, 8);
        pack_full_T<<<dim3(1024 / 32, 2048 / 32), blk>>>(W0r, W0i, P0, 512, 1024);
        pack_full_T<<<dim3(2048 / 32, 1024 / 32), blk>>>(W1r, W1i, P1, 1024, 512);
        pack_half_T<<<dim3(1024 / 32,  256 / 32), blk>>>(W2r, W2i, P2, 512, 256);
    }

    hopf_kernel<<<(BATCH * UNITS + 255) / 256, 256>>>(z, omega, bpar, st, out_z1);

    // layer 0: (8192 x 1024) @ (1024 x 2048)
    gemm_h<256, false><<<dim3(2048 / 256, MROWS / 128), 256, SM256>>>(
        st, P0, b0r, b0i, 1024, a1, 1024, 2048);
    // layer 1: (8192 x 2048) @ (2048 x 1024)
    gemm_h<256, false><<<dim3(1024 / 256, MROWS / 128), 256, SM256>>>(
        a1, P1, b1r, b1i, 512, a2, 2048, 1024);
    // layer 2: (8192 x 1024) @ (1024 x 256) -> scatter (batch, step, action)
    gemm_h<128, true><<<dim3(256 / 128, MROWS / 128), 256, SM128>>>(
        a2, P2, b2r, b2r, 256, out, 1024, 256);
}

// round 6
// speedup vs baseline: 8.0217x; 1.2675x over previous
#include <cuda_runtime.h>
#include <cuda_fp16.h>
#include <math.h>
#include <cstdint>

#define DT 0.001f
#define STEPS 128
#define UNITS 512
#define BATCH 64
#define MROWS (STEPS * BATCH)   // 8192
#define ACTION_DIM 256

// ---------------- scratch ----------------
__device__ __half g_states_h[MROWS * 1024];   // [x(512) | y(512)]
__device__ __half g_act1_h[MROWS * 2048];     // [x(1024) | y(1024)]
__device__ __half g_act2_h[MROWS * 1024];     // [x(512) | y(512)]
__device__ __half g_B0k[3 * 1024 * 512];      // layer0 karatsuba B: [3][N=1024][K=512]
__device__ __half g_B1k[3 * 512 * 1024];      // layer1: [3][512][1024]
__device__ __half g_P2h[256 * 1024];          // layer2: [N=256][2K=1024] = [Wr^T | -Wi^T]

__device__ __forceinline__ uint32_t smem_u32(const void* p) {
    uint32_t a;
    asm("{ .reg .u64 t; cvta.to.shared.u64 t, %1; cvt.u32.u64 %0, t; }" : "=r"(a) : "l"(p));
    return a;
}
__device__ __forceinline__ void cp16(uint32_t s, const void* g) {
    asm volatile("cp.async.cg.shared.global [%0], [%1], 16;" :: "r"(s), "l"(g));
}
__device__ __forceinline__ void ldm_x4(uint32_t* r, uint32_t addr) {
    asm volatile("ldmatrix.sync.aligned.m8n8.x4.shared.b16 {%0,%1,%2,%3}, [%4];"
                 : "=r"(r[0]), "=r"(r[1]), "=r"(r[2]), "=r"(r[3]) : "r"(addr));
}
__device__ __forceinline__ void mma_f16(float* c, const uint32_t* a, const uint32_t* b) {
    asm volatile(
        "mma.sync.aligned.m16n8k16.row.col.f32.f16.f16.f32 "
        "{%0,%1,%2,%3}, {%4,%5,%6,%7}, {%8,%9}, {%0,%1,%2,%3};"
        : "+f"(c[0]), "+f"(c[1]), "+f"(c[2]), "+f"(c[3])
        : "r"(a[0]), "r"(a[1]), "r"(a[2]), "r"(a[3]), "r"(b[0]), "r"(b[1]));
}
__device__ __forceinline__ uint32_t hadd2u(uint32_t a, uint32_t b) {
    __half2 r = __hadd2(*(__half2*)&a, *(__half2*)&b);
    return *(uint32_t*)&r;
}

// ---------------- weight packing ----------------
// Karatsuba pack: Bk[0][n][k]=Wr[k][n]; Bk[1]=Wi-Wr; Bk[2]=Wr+Wi. (W: [K][N] fp32)
__global__ void pack_kar(const float* __restrict__ Wr, const float* __restrict__ Wi,
                         __half* __restrict__ Bk, int K, int N) {
    __shared__ float tr[32][33], ti[32][33];
    int k0 = blockIdx.x * 32;
    int n0 = blockIdx.y * 32;
    int tx = threadIdx.x, ty0 = threadIdx.y;
#pragma unroll
    for (int i = 0; i < 4; i++) {
        int ty = ty0 + i * 8;
        tr[ty][tx] = Wr[(size_t)(k0 + ty) * N + n0 + tx];
        ti[ty][tx] = Wi[(size_t)(k0 + ty) * N + n0 + tx];
    }
    __syncthreads();
    const size_t NK = (size_t)N * K;
#pragma unroll
    for (int i = 0; i < 4; i++) {
        int ty = ty0 + i * 8;
        float wr = tr[tx][ty], wi = ti[tx][ty];
        size_t o = (size_t)(n0 + ty) * K + k0 + tx;
        Bk[o] = __float2half_rn(wr);
        Bk[NK + o] = __float2half_rn(wi - wr);
        Bk[2 * NK + o] = __float2half_rn(wr + wi);
    }
}
// layer2 pack: PT[n][k] = k<K ? Wr[k][n] : -Wi[k-K][n]
__global__ void pack_half_T(const float* __restrict__ Wr, const float* __restrict__ Wi,
                            __half* __restrict__ PT, int K, int N) {
    __shared__ float tile[32][33];
    int k0 = blockIdx.x * 32;
    int n0 = blockIdx.y * 32;
    int tx = threadIdx.x, ty0 = threadIdx.y;
#pragma unroll
    for (int i = 0; i < 4; i++) {
        int ty = ty0 + i * 8;
        int k = k0 + ty;
        float v = (k < K) ? Wr[(size_t)k * N + n0 + tx] : -Wi[(size_t)(k - K) * N + n0 + tx];
        tile[ty][tx] = v;
    }
    __syncthreads();
#pragma unroll
    for (int i = 0; i < 4; i++) {
        int ty = ty0 + i * 8;
        PT[(size_t)(n0 + ty) * (2 * K) + k0 + tx] = __float2half_rn(tile[tx][ty]);
    }
}

// ---------------- hopf chain ----------------
__global__ void hopf_kernel(const float* __restrict__ z0, const float* __restrict__ omega,
                            const float* __restrict__ bpar, __half* __restrict__ states,
                            float* __restrict__ out_z1) {
    int tid = blockIdx.x * blockDim.x + threadIdx.x;
    if (tid >= BATCH * UNITS) return;
    int bi = tid / UNITS;
    int i  = tid - bi * UNITS;
    float x = z0[bi * 1024 + i];
    float y = z0[bi * 1024 + UNITS + i];
    float w = omega[bi] * (float)(i + 1);
    float bb = bpar[bi * UNITS + i];
#pragma unroll 4
    for (int t = 0; t < STEPS; t++) {
        float r2 = x * x + y * y;
        float g = bb - r2;
        float dx = g * x - w * y;
        float dy = g * y + w * x;
        x += DT * dx;
        y += DT * dy;
        __half* row = states + ((size_t)(t * BATCH + bi)) * 1024;
        row[i] = __float2half_rn(x);
        row[UNITS + i] = __float2half_rn(y);
        if (t == 0) {
            out_z1[bi * 1024 + i] = x;
            out_z1[bi * 1024 + UNITS + i] = y;
        }
    }
}

// ---------------- Karatsuba complex GEMM + bias + tanh ----------------
// Act[M][2K] = [x|y]; Bk[3][N][K]; Out[M][2N] = [tanh(k1-k3+br) | tanh(k1+k2+bi)]
// k1 = (x+y)@Wr, k2 = x@(Wi-Wr), k3 = y@(Wr+Wi)
// CTA: M=128, Nreal=64. 8 warps 4(m)x2(n), warp tile 32x32. K chunk = 128 halves.
#define KAR_BUF 114688   // per-buffer smem: Ax 32K + Ay 32K + B 48K (+pad)
__global__ __launch_bounds__(256, 1)
void gemm_kar(const __half* __restrict__ Act, const __half* __restrict__ Bk,
              const float* __restrict__ br, const float* __restrict__ bi,
              __half* __restrict__ Out, int K, int N) {
    extern __shared__ char sm[];
    const uint32_t smb = smem_u32(sm);
    const int tid = threadIdx.x;
    const int wid = tid >> 5, lane = tid & 31;
    const int wm = wid >> 1, wn = wid & 1;
    const int g = lane >> 2, tq = lane & 3;
    const int lm = lane & 15, l16 = lane >> 4, fx = lane & 7;

    const int bm = blockIdx.y * 128;
    const int bn = blockIdx.x * 64;
    const int nch = K / 128;
    const int K2 = 2 * K;
    const size_t NK = (size_t)N * K;

    // copy indexing
    const int crow = tid >> 3;     // 0..31
    const int cslot = tid & 7;
    const uint32_t swz16 = (uint32_t)((cslot ^ (crow & 7)) << 4);

    float acc1[2][4][4], acc2[2][4][4], acc3[2][4][4];
#pragma unroll
    for (int mt = 0; mt < 2; mt++)
#pragma unroll
        for (int nt = 0; nt < 4; nt++)
#pragma unroll
            for (int r = 0; r < 4; r++) {
                acc1[mt][nt][r] = 0.0f; acc2[mt][nt][r] = 0.0f; acc3[mt][nt][r] = 0.0f;
            }

    auto issue = [&](int c) {
        const uint32_t base = smb + (uint32_t)(c & 1) * KAR_BUF;
        // A: x (op 0) and y (op 1): 128 rows x 2 panels
#pragma unroll
        for (int op = 0; op < 2; op++)
#pragma unroll
            for (int pan = 0; pan < 2; pan++)
#pragma unroll
                for (int it = 0; it < 4; it++) {
                    int row = crow + it * 32;
                    uint32_t s = base + op * 32768 + pan * 16384 + (uint32_t)row * 128 + swz16;
                    const __half* gp = Act + (size_t)(bm + row) * K2 + op * K +
                                       c * 128 + pan * 64 + cslot * 8;
                    cp16(s, gp);
                }
        // B: 3 mats x 64 rows x 2 panels
#pragma unroll
        for (int mat = 0; mat < 3; mat++)
#pragma unroll
            for (int pan = 0; pan < 2; pan++)
#pragma unroll
                for (int it = 0; it < 2; it++) {
                    int row = crow + it * 32;
                    uint32_t s = base + 65536 + mat * 16384 + pan * 8192 +
                                 (uint32_t)row * 128 + swz16;
                    const __half* gp = Bk + (size_t)mat * NK + (size_t)(bn + row) * K +
                                       c * 128 + pan * 64 + cslot * 8;
                    cp16(s, gp);
                }
        asm volatile("cp.async.commit_group;" ::: "memory");
    };

    issue(0);

    const uint32_t a_row = (uint32_t)(wm * 32 + lm) * 128;
    const uint32_t b_row = (uint32_t)(wn * 32 + lm) * 128;

    for (int c = 0; c < nch; c++) {
        asm volatile("cp.async.wait_group 0;" ::: "memory");
        __syncthreads();
        if (c + 1 < nch) issue(c + 1);
        const uint32_t cb = smb + (uint32_t)(c & 1) * KAR_BUF;

#pragma unroll
        for (int kk = 0; kk < 8; kk++) {
            const int pan = kk >> 2, ks = kk & 3;
            const uint32_t kslot = (uint32_t)(((ks * 2 + l16) ^ fx) << 4);
            uint32_t af[2][2][4];   // [op x/y][mt][frag]
            const uint32_t ab = cb + pan * 16384 + a_row + kslot;
            ldm_x4(af[0][0], ab);
            ldm_x4(af[0][1], ab + 16 * 128);
            ldm_x4(af[1][0], ab + 32768);
            ldm_x4(af[1][1], ab + 32768 + 16 * 128);
            uint32_t bf[3][4][2];
            const uint32_t bb = cb + 65536 + pan * 8192 + b_row + kslot;
#pragma unroll
            for (int mat = 0; mat < 3; mat++) {
                uint32_t r[4];
                ldm_x4(r, bb + mat * 16384);
                bf[mat][0][0] = r[0]; bf[mat][1][0] = r[1];
                bf[mat][0][1] = r[2]; bf[mat][1][1] = r[3];
                ldm_x4(r, bb + mat * 16384 + 16 * 128);
                bf[mat][2][0] = r[0]; bf[mat][3][0] = r[1];
                bf[mat][2][1] = r[2]; bf[mat][3][1] = r[3];
            }
            uint32_t as[2][4];      // x+y fragments
#pragma unroll
            for (int mt = 0; mt < 2; mt++)
#pragma unroll
                for (int i = 0; i < 4; i++)
                    as[mt][i] = hadd2u(af[0][mt][i], af[1][mt][i]);
#pragma unroll
            for (int mt = 0; mt < 2; mt++)
#pragma unroll
                for (int nt = 0; nt < 4; nt++) {
                    mma_f16(acc1[mt][nt], as[mt],    bf[0][nt]);   // k1: (x+y)@Wr
                    mma_f16(acc2[mt][nt], af[0][mt], bf[1][nt]);   // k2: x@(Wi-Wr)
                    mma_f16(acc3[mt][nt], af[1][mt], bf[2][nt]);   // k3: y@(Wr+Wi)
                }
        }
    }

    // epilogue: xr = tanh(k1-k3+br), yi = tanh(k1+k2+bi)
#pragma unroll
    for (int mt = 0; mt < 2; mt++) {
        const int row0 = bm + wm * 32 + mt * 16 + g;
#pragma unroll
        for (int nt = 0; nt < 4; nt++) {
            const int col = bn + wn * 32 + nt * 8 + 2 * tq;
            const float br0 = br[col], br1 = br[col + 1];
            const float bi0 = bi[col], bi1 = bi[col + 1];
            const float* a1 = acc1[mt][nt];
            const float* a2 = acc2[mt][nt];
            const float* a3 = acc3[mt][nt];
            const float x0 = tanhf(a1[0] - a3[0] + br0);
            const float x1 = tanhf(a1[1] - a3[1] + br1);
            const float x2 = tanhf(a1[2] - a3[2] + br0);
            const float x3 = tanhf(a1[3] - a3[3] + br1);
            const float y0 = tanhf(a1[0] + a2[0] + bi0);
            const float y1 = tanhf(a1[1] + a2[1] + bi1);
            const float y2 = tanhf(a1[2] + a2[2] + bi0);
            const float y3 = tanhf(a1[3] + a2[3] + bi1);
            __half* o0 = Out + (size_t)row0 * (2 * N) + col;
            __half* o1 = Out + (size_t)(row0 + 8) * (2 * N) + col;
            *(__half2*)o0 = __floats2half2_rn(x0, x1);
            *(__half2*)o1 = __floats2half2_rn(x2, x3);
            *(__half2*)(o0 + N) = __floats2half2_rn(y0, y1);
            *(__half2*)(o1 + N) = __floats2half2_rn(y2, y3);
        }
    }
}

// ---------------- layer-2 fp16 GEMM (real half only) + bias + tanh + scatter ----------------
#define L2_CHUNK (128 * 128 + 128 * 128)     // A + B bytes per 64-half chunk
#define L2_PAIR (2 * L2_CHUNK)
__global__ __launch_bounds__(256, 1)
void gemm_l2(const __half* __restrict__ A, const __half* __restrict__ Bw,
             const float* __restrict__ bias, float* __restrict__ C, int K) {
    constexpr int NTN = 4;
    extern __shared__ char sm[];
    const uint32_t smb = smem_u32(sm);
    const int tid = threadIdx.x;
    const int wid = tid >> 5, lane = tid & 31;
    const int wm = wid >> 2, wn = wid & 3;
    const int g = lane >> 2, tq = lane & 3;

    const int bm = blockIdx.y * 128;
    const int bn = blockIdx.x * 128;
    const int nk2 = K / 128;

    const int cr0 = tid >> 3;
    const int cs = tid & 7;
    const uint32_t cswz = (uint32_t)((cs ^ (cr0 & 7)) << 4);
    const __half* Agb = A  + (size_t)(bm + cr0) * K + cs * 8;
    const __half* Bgb = Bw + (size_t)(bn + cr0) * K + cs * 8;

    float acc[4][NTN][4];
#pragma unroll
    for (int mt = 0; mt < 4; mt++)
#pragma unroll
        for (int nt = 0; nt < NTN; nt++)
#pragma unroll
            for (int r = 0; r < 4; r++) acc[mt][nt][r] = 0.0f;

    auto issue_pair = [&](int p) {
        const uint32_t base = smb + (uint32_t)(p & 1) * L2_PAIR;
#pragma unroll
        for (int sub = 0; sub < 2; sub++) {
            const uint32_t sa = base + sub * L2_CHUNK;
            const uint32_t sb = sa + 128 * 128;
            const __half* Ac = Agb + (2 * p + sub) * 64;
            const __half* Bc = Bgb + (2 * p + sub) * 64;
#pragma unroll
            for (int it = 0; it < 4; it++) {
                cp16(sa + (uint32_t)(cr0 + it * 32) * 128 + cswz, Ac + (size_t)it * 32 * K);
                cp16(sb + (uint32_t)(cr0 + it * 32) * 128 + cswz, Bc + (size_t)it * 32 * K);
            }
        }
        asm volatile("cp.async.commit_group;" ::: "memory");
    };

    const int lm = lane & 15;
    const int l16 = lane >> 4;
    const int fx = lane & 7;
    const uint32_t a_rowoff = (uint32_t)(wm * 64 + lm) * 128;
    const uint32_t b_rowoff = (uint32_t)(wn * 32 + lm) * 128;

    issue_pair(0);

    for (int c2 = 0; c2 < nk2; c2++) {
        asm volatile("cp.async.wait_group 0;" ::: "memory");
        __syncthreads();
        if (c2 + 1 < nk2) issue_pair(c2 + 1);
        const uint32_t pbase = smb + (uint32_t)(c2 & 1) * L2_PAIR;

#pragma unroll
        for (int kk = 0; kk < 8; kk++) {
            const uint32_t cb = pbase + (uint32_t)(kk >> 2) * L2_CHUNK;
            const int ks = kk & 3;
            const uint32_t kslot = (uint32_t)(((ks * 2 + l16) ^ fx) << 4);
            uint32_t af[4][4];
#pragma unroll
            for (int mt = 0; mt < 4; mt++)
                ldm_x4(af[mt], cb + a_rowoff + (uint32_t)(mt * 16) * 128 + kslot);
            uint32_t bf[NTN][2];
#pragma unroll
            for (int p = 0; p < NTN / 2; p++) {
                uint32_t r[4];
                ldm_x4(r, cb + 128 * 128 + b_rowoff + (uint32_t)(p * 16) * 128 + kslot);
                bf[2 * p][0] = r[0]; bf[2 * p + 1][0] = r[1];
                bf[2 * p][1] = r[2]; bf[2 * p + 1][1] = r[3];
            }
#pragma unroll
            for (int mt = 0; mt < 4; mt++)
#pragma unroll
                for (int nt = 0; nt < NTN; nt++)
                    mma_f16(acc[mt][nt], af[mt], bf[nt]);
        }
    }

#pragma unroll
    for (int mt = 0; mt < 4; mt++) {
        const int row0 = bm + wm * 64 + mt * 16 + g;
#pragma unroll
        for (int nt = 0; nt < NTN; nt++) {
            const int col = bn + wn * 32 + nt * 8 + 2 * tq;
            const float bv0 = bias[col], bv1 = bias[col + 1];
            const float v0 = tanhf(acc[mt][nt][0] + bv0);
            const float v1 = tanhf(acc[mt][nt][1] + bv1);
            const float v2 = tanhf(acc[mt][nt][2] + bv0);
            const float v3 = tanhf(acc[mt][nt][3] + bv1);
            const int t0 = row0 >> 6, b0 = row0 & 63;
            const int r1 = row0 + 8;
            const int t1 = r1 >> 6, b1 = r1 & 63;
            *(float2*)(C + (size_t)b0 * (STEPS * ACTION_DIM) + t0 * ACTION_DIM + col) =
                make_float2(v0, v1);
            *(float2*)(C + (size_t)b1 * (STEPS * ACTION_DIM) + t1 * ACTION_DIM + col) =
                make_float2(v2, v3);
        }
    }
}

// ---------------- launch ----------------
extern "C" void kernel_launch(void* const* d_in, const int* in_sizes, int n_in,
                              void* d_out, int out_size) {
    const float* z     = (const float*)d_in[0];
    const float* omega = (const float*)d_in[1];
    const float* bpar  = (const float*)d_in[2];
    const float* W0r = (const float*)d_in[3];
    const float* W0i = (const float*)d_in[4];
    const float* b0r = (const float*)d_in[5];
    const float* b0i = (const float*)d_in[6];
    const float* W1r = (const float*)d_in[7];
    const float* W1i = (const float*)d_in[8];
    const float* b1r = (const float*)d_in[9];
    const float* b1i = (const float*)d_in[10];
    const float* W2r = (const float*)d_in[11];
    const float* W2i = (const float*)d_in[12];
    const float* b2r = (const float*)d_in[13];

    float* out = (float*)d_out;                                 // (64, 128, 256)
    float* out_z1 = out + (size_t)BATCH * STEPS * ACTION_DIM;   // (64, 1024)

    __half *B0, *B1, *P2, *st, *a1, *a2;
    cudaGetSymbolAddress((void**)&B0, g_B0k);
    cudaGetSymbolAddress((void**)&B1, g_B1k);
    cudaGetSymbolAddress((void**)&P2, g_P2h);
    cudaGetSymbolAddress((void**)&st, g_states_h);
    cudaGetSymbolAddress((void**)&a1, g_act1_h);
    cudaGetSymbolAddress((void**)&a2, g_act2_h);

    constexpr int SM_KAR = 2 * KAR_BUF;      // 229376
    constexpr int SM_L2 = 2 * L2_PAIR;       // 131072
    cudaFuncSetAttribute(gemm_kar, cudaFuncAttributeMaxDynamicSharedMemorySize, SM_KAR);
    cudaFuncSetAttribute(gemm_l2, cudaFuncAttributeMaxDynamicSharedMemorySize, SM_L2);

    {
        dim3 blk(32, 8);
        pack_kar<<<dim3(512 / 32, 1024 / 32), blk>>>(W0r, W0i, B0, 512, 1024);
        pack_kar<<<dim3(1024 / 32, 512 / 32), blk>>>(W1r, W1i, B1, 1024, 512);
        pack_half_T<<<dim3(1024 / 32, 256 / 32), blk>>>(W2r, W2i, P2, 512, 256);
    }

    hopf_kernel<<<(BATCH * UNITS + 255) / 256, 256>>>(z, omega, bpar, st, out_z1);

    // layer 0: K=512, N=1024 -> act1 [8192][2048]
    gemm_kar<<<dim3(1024 / 64, MROWS / 128), 256, SM_KAR>>>(st, B0, b0r, b0i, a1, 512, 1024);
    // layer 1: K=1024, N=512 -> act2 [8192][1024]
    gemm_kar<<<dim3(512 / 64, MROWS / 128), 256, SM_KAR>>>(a1, B1, b1r, b1i, a2, 1024, 512);
    // layer 2: real half only, scatter to (batch, step, action)
    gemm_l2<<<dim3(256 / 128, MROWS / 128), 256, SM_L2>>>(a2, P2, b2r, out, 1024);
}